// round 4
// baseline (speedup 1.0000x reference)
#include <cuda_runtime.h>
#include <stdint.h>

#define MAX_B        64
#define BM_WORDS_MAX 32768   // supports num_nodes up to 1,048,576
#define CHUNK_ELEMS  1024    // 256 threads * 4 floats

__device__ unsigned int g_bitmap[BM_WORDS_MAX];
__device__ int          g_keys[MAX_B];
__device__ float        g_rowsum[MAX_B];

// ---------------------------------------------------------------------------
// K1: zero bitmap + row sums, then set query keys and bitmap bits.
// Single block. Deterministic each launch (graph replay safe).
// Inputs are int32 (JAX x64 disabled: jnp.int64 request silently -> int32).
// ---------------------------------------------------------------------------
__global__ void prep_kernel(const int* __restrict__ batch, int B, int bmWords) {
    for (int i = threadIdx.x; i < bmWords; i += blockDim.x) g_bitmap[i] = 0u;
    if (threadIdx.x < MAX_B) g_rowsum[threadIdx.x] = 0.0f;
    __syncthreads();
    if (threadIdx.x < B) {
        int h = batch[threadIdx.x * 96 + 0];   // batch[b,0,0]
        int r = batch[threadIdx.x * 96 + 2];   // batch[b,0,2]
        g_keys[threadIdx.x] = (h << 9) | r;    // r < 512
        atomicOr(&g_bitmap[h >> 5], 1u << (h & 31));
    }
}

// ---------------------------------------------------------------------------
// K2: zero the output buffer (d_out poisoned to 0xAA), including any
// trailing ALPHA slot.
// ---------------------------------------------------------------------------
__global__ void zero_kernel(float* __restrict__ out, int n4, int n) {
    int i = blockIdx.x * blockDim.x + threadIdx.x;
    if (i < n4) reinterpret_cast<float4*>(out)[i] = make_float4(0.f, 0.f, 0.f, 0.f);
    int t = n4 * 4 + i;
    if (t < n && i < (n - n4 * 4)) out[t] = 0.0f;
}

// ---------------------------------------------------------------------------
// K3: edge scan. Bitmap prefilter on head; on rare hit, compare the packed
// (head,type) key against all B queries and atomicAdd weight into dist.
// Only the heads stream (4 MB, int32) is fully read; type/tail/weight loads
// happen on bitmap hits only.
// ---------------------------------------------------------------------------
__device__ __forceinline__ void handle_edge(
    int e, int h,
    const unsigned int* __restrict__ bm,
    const int* __restrict__ skeys,
    const int* __restrict__ etype,
    const int* __restrict__ tails,
    const float* __restrict__ w,
    float* __restrict__ out,
    int B, int nn)
{
    if ((unsigned)h < (unsigned)nn && (bm[h >> 5] & (1u << (h & 31)))) {
        int key  = (h << 9) | etype[e];
        int tail = tails[e];
        float wt = w[e];
        if ((unsigned)tail < (unsigned)nn) {
            for (int b = 0; b < B; b++)
                if (skeys[b] == key)
                    atomicAdd(&out[(size_t)b * nn + tail], wt);
        }
    }
}

__global__ void scan_kernel(const int* __restrict__ heads,
                            const int* __restrict__ etype,
                            const int* __restrict__ tails,
                            const float* __restrict__ w,
                            float* __restrict__ out,
                            int E, int B, int bmWords, int nn) {
    __shared__ unsigned int sbm[2048];
    __shared__ int skeys[MAX_B];
    const unsigned int* bm = g_bitmap;
    if (bmWords <= 2048) {
        for (int i = threadIdx.x; i < bmWords; i += blockDim.x) sbm[i] = g_bitmap[i];
        bm = sbm;
    }
    if (threadIdx.x < B) skeys[threadIdx.x] = g_keys[threadIdx.x];
    __syncthreads();

    const int4* h4 = reinterpret_cast<const int4*>(heads);
    int nQuads = E >> 2;
    int stride = gridDim.x * blockDim.x;
    for (int q = blockIdx.x * blockDim.x + threadIdx.x; q < nQuads; q += stride) {
        int4 hh = h4[q];
        int e = 4 * q;
        handle_edge(e + 0, hh.x, bm, skeys, etype, tails, w, out, B, nn);
        handle_edge(e + 1, hh.y, bm, skeys, etype, tails, w, out, B, nn);
        handle_edge(e + 2, hh.z, bm, skeys, etype, tails, w, out, B, nn);
        handle_edge(e + 3, hh.w, bm, skeys, etype, tails, w, out, B, nn);
    }
    // tail edges (E not divisible by 4)
    if (blockIdx.x == 0 && threadIdx.x < (E & 3)) {
        int e = (nQuads << 2) + threadIdx.x;
        handle_edge(e, heads[e], bm, skeys, etype, tails, w, out, B, nn);
    }
}

// exp term with zero-skip: dist values are small non-negative counts, so no
// max subtraction needed (exp cannot overflow), and exp(0)==1 exactly —
// mathematically identical to jax.nn.softmax on this data.
__device__ __forceinline__ float expterm(float v) {
    return (v == 0.0f) ? 1.0f : __expf(v);
}

// ---------------------------------------------------------------------------
// K4a: per-(row,chunk) partial sum of exp terms -> atomicAdd into g_rowsum.
// ---------------------------------------------------------------------------
__global__ void sum_kernel(const float* __restrict__ out, int nn, int chunks) {
    int b = blockIdx.x / chunks;
    int c = blockIdx.x % chunks;
    const float* row = out + (size_t)b * nn;
    float s = 0.0f;
    if ((nn & 3) == 0) {
        int i4 = c * (CHUNK_ELEMS / 4) + threadIdx.x;
        if (i4 < nn / 4) {
            float4 v = reinterpret_cast<const float4*>(row)[i4];
            s = expterm(v.x) + expterm(v.y) + expterm(v.z) + expterm(v.w);
        }
    } else {
        int base = c * CHUNK_ELEMS;
        #pragma unroll
        for (int j = 0; j < 4; j++) {
            int i = base + threadIdx.x + j * 256;
            if (i < nn) s += expterm(row[i]);
        }
    }
    // block reduce
    #pragma unroll
    for (int o = 16; o > 0; o >>= 1) s += __shfl_xor_sync(0xFFFFFFFFu, s, o);
    __shared__ float red[8];
    if ((threadIdx.x & 31) == 0) red[threadIdx.x >> 5] = s;
    __syncthreads();
    if (threadIdx.x < 8) {
        float v = red[threadIdx.x];
        #pragma unroll
        for (int o = 4; o > 0; o >>= 1) v += __shfl_xor_sync(0xFFu, v, o);
        if (threadIdx.x == 0) atomicAdd(&g_rowsum[b], v);
    }
}

// ---------------------------------------------------------------------------
// K4b: normalized write pass: out[i] = expterm(out[i]) / rowsum[b].
// ---------------------------------------------------------------------------
__global__ void write_kernel(float* __restrict__ out, int nn, int chunks) {
    int b = blockIdx.x / chunks;
    int c = blockIdx.x % chunks;
    __shared__ float s_inv;
    if (threadIdx.x == 0) s_inv = 1.0f / g_rowsum[b];
    __syncthreads();
    float inv = s_inv;
    float* row = out + (size_t)b * nn;
    if ((nn & 3) == 0) {
        int i4 = c * (CHUNK_ELEMS / 4) + threadIdx.x;
        if (i4 < nn / 4) {
            float4 v = reinterpret_cast<float4*>(row)[i4];
            v.x = expterm(v.x) * inv;
            v.y = expterm(v.y) * inv;
            v.z = expterm(v.z) * inv;
            v.w = expterm(v.w) * inv;
            reinterpret_cast<float4*>(row)[i4] = v;
        }
    } else {
        int base = c * CHUNK_ELEMS;
        #pragma unroll
        for (int j = 0; j < 4; j++) {
            int i = base + threadIdx.x + j * 256;
            if (i < nn) row[i] = expterm(row[i]) * inv;
        }
    }
}

extern "C" void kernel_launch(void* const* d_in, const int* in_sizes, int n_in,
                              void* d_out, int out_size) {
    // ---- Identify inputs by SIZE SIGNATURE (ordering-invariant) ----
    // edge_index : unique largest (2E elements, int32)
    // batch      : divisible by 96 (B*32*3 elements, int32)
    // edge_type  : first of the two size-E inputs  (precedes weight in both
    // edge_weight: second of the two size-E inputs  dict and alpha order)
    // num_nodes  : size-1 input (ignored; nn derived from out_size)
    int iEI = 0, maxSz = 0;
    for (int i = 0; i < n_in; i++)
        if (in_sizes[i] > maxSz) { maxSz = in_sizes[i]; iEI = i; }
    int E = maxSz / 2;

    int iB = -1, iT = -1, iW = -1;
    for (int i = 0; i < n_in; i++) {
        if (i == iEI) continue;
        int s = in_sizes[i];
        if (s == E)                               { if (iT < 0) iT = i; else iW = i; }
        else if (s > 1 && (s % 96) == 0 && iB < 0) iB = i;
    }

    const int*   edge_index = (const int*)d_in[iEI];
    const int*   edge_type  = (const int*)d_in[iT];
    const int*   batch      = (const int*)d_in[iB];
    const float* edge_w     = (const float*)d_in[iW];

    int B  = in_sizes[iB] / 96;       // 64
    int nn = out_size / B;            // 50000 (int div absorbs trailing ALPHA slot)
    const int* heads = edge_index;
    const int* tails = edge_index + E;

    int bmWords = (nn + 31) / 32;

    // K1: prep
    prep_kernel<<<1, 256>>>(batch, B, bmWords);

    // K2: zero full output (including ALPHA tail)
    int n4 = out_size / 4;
    int tailN = out_size - n4 * 4;
    int zb = ((n4 > tailN ? n4 : tailN) + 255) / 256;
    zero_kernel<<<zb, 256>>>((float*)d_out, n4, out_size);

    // K3: edge scan (grid-stride, ~4 quads per thread)
    int nQuads = E >> 2;
    int sb = (nQuads + 256 * 4 - 1) / (256 * 4);
    if (sb < 1) sb = 1;
    scan_kernel<<<sb, 256>>>(heads, edge_type, tails, edge_w,
                             (float*)d_out, E, B, bmWords, nn);

    // K4: softmax (no-max, zero-skip-exp), chunked
    int chunks = (nn + CHUNK_ELEMS - 1) / CHUNK_ELEMS;
    sum_kernel<<<B * chunks, 256>>>((const float*)d_out, nn, chunks);
    write_kernel<<<B * chunks, 256>>>((float*)d_out, nn, chunks);
}

// round 5
// speedup vs baseline: 1.1008x; 1.1008x over previous
#include <cuda_runtime.h>
#include <stdint.h>

#define MAX_B        64
#define BM_WORDS_MAX 32768   // supports num_nodes up to 1,048,576
#define CAP          8192    // max recorded hits (expected ~5)

__device__ unsigned int g_bitmap[BM_WORDS_MAX];
__device__ int          g_keys[MAX_B];
__device__ float        g_adj[MAX_B];     // sum over unique hits of (exp(v)-1)
__device__ int          g_nhits;
__device__ int          g_done_fill;
__device__ int          g_hit_b[CAP];
__device__ int          g_hit_t[CAP];
__device__ float        g_hit_w[CAP];

// ---------------------------------------------------------------------------
// K1: reset all state; build query keys + head bitmap. Single block.
// Graph-replay safe: fully re-initializes every __device__ global each call.
// ---------------------------------------------------------------------------
__global__ void prep_kernel(const int* __restrict__ batch, int B, int bmWords) {
    for (int i = threadIdx.x; i < bmWords; i += blockDim.x) g_bitmap[i] = 0u;
    if (threadIdx.x < MAX_B) g_adj[threadIdx.x] = 0.0f;
    if (threadIdx.x == 0) { g_nhits = 0; g_done_fill = 0; }
    __syncthreads();
    if (threadIdx.x < B) {
        int h = batch[threadIdx.x * 96 + 0];   // batch[b,0,0]
        int r = batch[threadIdx.x * 96 + 2];   // batch[b,0,2]
        g_keys[threadIdx.x] = (h << 9) | r;    // num_rels < 512
        atomicOr(&g_bitmap[h >> 5], 1u << (h & 31));
    }
}

// ---------------------------------------------------------------------------
// K2: edge scan. Bitmap prefilter on head (only the 4 MB heads stream is
// fully read); rare hits are appended to a global list. The LAST block to
// finish aggregates duplicates and computes g_adj[b] = sum(exp(v)-1).
// ---------------------------------------------------------------------------
__device__ __forceinline__ void handle_edge(
    int e, int h,
    const unsigned int* __restrict__ bm,
    const int* __restrict__ skeys,
    const int* __restrict__ etype,
    const int* __restrict__ tails,
    const float* __restrict__ w,
    int B, int nn)
{
    if ((unsigned)h < (unsigned)nn && (bm[h >> 5] & (1u << (h & 31)))) {
        int key  = (h << 9) | etype[e];
        int tail = tails[e];
        float wt = w[e];
        if ((unsigned)tail < (unsigned)nn) {
            for (int b = 0; b < B; b++) {
                if (skeys[b] == key) {
                    int idx = atomicAdd(&g_nhits, 1);
                    if (idx < CAP) {
                        g_hit_b[idx] = b;
                        g_hit_t[idx] = tail;
                        g_hit_w[idx] = wt;
                    }
                }
            }
        }
    }
}

__device__ int g_done_scan;

__global__ void scan_kernel(const int* __restrict__ heads,
                            const int* __restrict__ etype,
                            const int* __restrict__ tails,
                            const float* __restrict__ w,
                            int E, int B, int bmWords, int nn) {
    __shared__ unsigned int sbm[2048];
    __shared__ int skeys[MAX_B];
    const unsigned int* bm = g_bitmap;
    if (bmWords <= 2048) {
        for (int i = threadIdx.x; i < bmWords; i += blockDim.x) sbm[i] = g_bitmap[i];
        bm = sbm;
    }
    if (threadIdx.x < B) skeys[threadIdx.x] = g_keys[threadIdx.x];
    __syncthreads();

    const int4* h4 = reinterpret_cast<const int4*>(heads);
    int nQuads = E >> 2;
    int stride = gridDim.x * blockDim.x;
    for (int q = blockIdx.x * blockDim.x + threadIdx.x; q < nQuads; q += stride) {
        int4 hh = h4[q];
        int e = 4 * q;
        handle_edge(e + 0, hh.x, bm, skeys, etype, tails, w, B, nn);
        handle_edge(e + 1, hh.y, bm, skeys, etype, tails, w, B, nn);
        handle_edge(e + 2, hh.z, bm, skeys, etype, tails, w, B, nn);
        handle_edge(e + 3, hh.w, bm, skeys, etype, tails, w, B, nn);
    }
    if (blockIdx.x == 0 && threadIdx.x < (E & 3)) {
        int e = (nQuads << 2) + threadIdx.x;
        handle_edge(e, heads[e], bm, skeys, etype, tails, w, B, nn);
    }

    // --- last-block aggregation: dedupe hits, accumulate exp(v)-1 per row ---
    __threadfence();
    __syncthreads();
    __shared__ int s_last;
    if (threadIdx.x == 0)
        s_last = (atomicAdd(&g_done_scan, 1) == gridDim.x - 1) ? 1 : 0;
    __syncthreads();
    if (s_last) {
        if (threadIdx.x == 0) g_done_scan = 0;   // reset for next replay
        int n = atomicAdd(&g_nhits, 0);
        if (n > CAP) n = CAP;
        for (int i = threadIdx.x; i < n; i += blockDim.x) {
            int b = g_hit_b[i], t = g_hit_t[i];
            float v = g_hit_w[i];
            bool owner = true;
            for (int j = 0; j < n; j++) {
                if (j == i) continue;
                if (g_hit_b[j] == b && g_hit_t[j] == t) {
                    if (j < i) { owner = false; break; }
                    v += g_hit_w[j];
                }
            }
            if (owner) atomicAdd(&g_adj[b], __expf(v) - 1.0f);
        }
    }
}

// ---------------------------------------------------------------------------
// K3: fill output with per-row constant 1/S_b (store-only, bandwidth-bound).
// The LAST block then overwrites the few hit entries with exp(v)/S_b and
// zeroes any trailing ALPHA slot.
// Grid: (chunksPerRow, B). Each block stores 2048 floats of one row.
// ---------------------------------------------------------------------------
__global__ void fill_kernel(float* __restrict__ out, int nn, int out_size, int B) {
    int b = blockIdx.y;
    __shared__ float s_inv;
    if (threadIdx.x == 0) s_inv = 1.0f / ((float)nn + g_adj[b]);
    __syncthreads();
    float inv = s_inv;
    float* row = out + (size_t)b * nn;

    if ((nn & 3) == 0) {
        int n4 = nn >> 2;
        int base = blockIdx.x * 512;         // 512 float4 per block
        float4 v4 = make_float4(inv, inv, inv, inv);
        #pragma unroll
        for (int j = 0; j < 2; j++) {
            int i4 = base + threadIdx.x + j * 256;
            if (i4 < n4) reinterpret_cast<float4*>(row)[i4] = v4;
        }
    } else {
        int base = blockIdx.x * 2048;
        #pragma unroll
        for (int j = 0; j < 8; j++) {
            int i = base + threadIdx.x + j * 256;
            if (i < nn) row[i] = inv;
        }
    }

    // --- last-block fixup ---
    __threadfence();
    __syncthreads();
    __shared__ int s_last;
    if (threadIdx.x == 0)
        s_last = (atomicAdd(&g_done_fill, 1) == gridDim.x * gridDim.y - 1) ? 1 : 0;
    __syncthreads();
    if (s_last) {
        // trailing ALPHA slot(s)
        for (int t = B * nn + threadIdx.x; t < out_size; t += blockDim.x)
            out[t] = 0.0f;
        int n = atomicAdd(&g_nhits, 0);
        if (n > CAP) n = CAP;
        for (int i = threadIdx.x; i < n; i += blockDim.x) {
            int hb = g_hit_b[i], ht = g_hit_t[i];
            float v = g_hit_w[i];
            bool owner = true;
            for (int j = 0; j < n; j++) {
                if (j == i) continue;
                if (g_hit_b[j] == hb && g_hit_t[j] == ht) {
                    if (j < i) { owner = false; break; }
                    v += g_hit_w[j];
                }
            }
            if (owner)
                out[(size_t)hb * nn + ht] = __expf(v) / ((float)nn + g_adj[hb]);
        }
    }
}

extern "C" void kernel_launch(void* const* d_in, const int* in_sizes, int n_in,
                              void* d_out, int out_size) {
    // ---- Identify inputs by SIZE SIGNATURE (ordering-invariant) ----
    int iEI = 0, maxSz = 0;
    for (int i = 0; i < n_in; i++)
        if (in_sizes[i] > maxSz) { maxSz = in_sizes[i]; iEI = i; }
    int E = maxSz / 2;

    int iB = -1, iT = -1, iW = -1;
    for (int i = 0; i < n_in; i++) {
        if (i == iEI) continue;
        int s = in_sizes[i];
        if (s == E)                               { if (iT < 0) iT = i; else iW = i; }
        else if (s > 1 && (s % 96) == 0 && iB < 0) iB = i;
    }

    const int*   edge_index = (const int*)d_in[iEI];
    const int*   edge_type  = (const int*)d_in[iT];
    const int*   batch      = (const int*)d_in[iB];
    const float* edge_w     = (const float*)d_in[iW];

    int B  = in_sizes[iB] / 96;       // 64
    int nn = out_size / B;            // 50000 (int div absorbs trailing ALPHA slot)
    const int* heads = edge_index;
    const int* tails = edge_index + E;

    int bmWords = (nn + 31) / 32;

    // K1: prep/reset
    prep_kernel<<<1, 256>>>(batch, B, bmWords);

    // K2: edge scan + last-block aggregation
    int nQuads = E >> 2;
    int sb = (nQuads + 256 * 4 - 1) / (256 * 4);
    if (sb < 1) sb = 1;
    scan_kernel<<<sb, 256>>>(heads, edge_type, tails, edge_w, E, B, bmWords, nn);

    // K3: constant fill + last-block fixup
    int chunks = (nn + 2047) / 2048;
    dim3 fg(chunks, B);
    fill_kernel<<<fg, 256>>>((float*)d_out, nn, out_size, B);
}

// round 6
// speedup vs baseline: 1.1497x; 1.0444x over previous
#include <cuda_runtime.h>
#include <stdint.h>

#define MAX_B     64
#define CAP       8192     // max recorded hits (expected ~5)
#define BM_WORDS  2048     // 65536-bit hashed head bitmap (exact for nn<=65536)
#define NTHREADS  256
#define NBLOCKS   592      // <= guaranteed co-resident (8.7KB smem, 256thr)

// All statically zero-initialized. Protocol: end-of-kernel reset restores the
// zero state for the next (graph-replayed) launch, so every launch starts clean.
__device__ int          g_nhits;
__device__ int          g_hit_b[CAP];
__device__ int          g_hit_t[CAP];
__device__ float        g_hit_w[CAP];
__device__ float        g_inv[MAX_B];      // 1 / S_b
__device__ int          g_nfix;
__device__ long long    g_fix_pos[CAP];
__device__ float        g_fix_val[CAP];
__device__ int          g_done1, g_done2;
__device__ volatile int g_phase;

__global__ void __launch_bounds__(NTHREADS, 1)
fused_kernel(const int* __restrict__ heads,
             const int* __restrict__ etype,
             const int* __restrict__ tails,
             const float* __restrict__ w,
             const int* __restrict__ batch,
             float* __restrict__ out,
             int E, int B, int nn, int out_size)
{
    __shared__ unsigned int sbm[BM_WORDS];
    __shared__ int   skeys[MAX_B];
    __shared__ float sinv[MAX_B];
    __shared__ float sadj[MAX_B];
    __shared__ int   s_flag;

    const int tid = threadIdx.x;
    const int bid = blockIdx.x;
    const int nb  = gridDim.x;

    // ---------------- Phase A: per-block bitmap + query keys -------------
    for (int i = tid; i < BM_WORDS; i += NTHREADS) sbm[i] = 0u;
    __syncthreads();
    if (tid < B) {
        int h = batch[tid * 96 + 0];        // batch[b,0,0]
        int r = batch[tid * 96 + 2];        // batch[b,0,2]
        skeys[tid] = (h << 9) | r;          // num_rels < 512
        atomicOr(&sbm[(h & 0xFFFF) >> 5], 1u << (h & 31));
    }
    __syncthreads();

    // ---------------- Phase B: blocked edge scan --------------------------
    {
        const int4* h4 = reinterpret_cast<const int4*>(heads);
        int nQuads = E >> 2;
        int per = (nQuads + nb - 1) / nb;
        int s = bid * per;
        int e = s + per; if (e > nQuads) e = nQuads;
        for (int q = s + tid; q < e; q += NTHREADS) {
            int4 hh = h4[q];
            int ebase = 4 * q;
            #pragma unroll
            for (int j = 0; j < 4; j++) {
                int h = (j == 0) ? hh.x : (j == 1) ? hh.y : (j == 2) ? hh.z : hh.w;
                if (sbm[(h & 0xFFFF) >> 5] & (1u << (h & 31))) {
                    int eidx = ebase + j;
                    int key  = (h << 9) | etype[eidx];
                    int tail = tails[eidx];
                    float wt = w[eidx];
                    if ((unsigned)tail < (unsigned)nn && (unsigned)h < (unsigned)nn) {
                        for (int b = 0; b < B; b++) {
                            if (skeys[b] == key) {
                                int idx = atomicAdd(&g_nhits, 1);
                                if (idx < CAP) {
                                    g_hit_b[idx] = b;
                                    g_hit_t[idx] = tail;
                                    g_hit_w[idx] = wt;
                                }
                            }
                        }
                    }
                }
            }
        }
        // tail edges (E % 4)
        if (bid == 0 && tid < (E & 3)) {
            int eidx = (nQuads << 2) + tid;
            int h = heads[eidx];
            if (sbm[(h & 0xFFFF) >> 5] & (1u << (h & 31))) {
                int key  = (h << 9) | etype[eidx];
                int tail = tails[eidx];
                float wt = w[eidx];
                if ((unsigned)tail < (unsigned)nn && (unsigned)h < (unsigned)nn) {
                    for (int b = 0; b < B; b++) {
                        if (skeys[b] == key) {
                            int idx = atomicAdd(&g_nhits, 1);
                            if (idx < CAP) {
                                g_hit_b[idx] = b;
                                g_hit_t[idx] = tail;
                                g_hit_w[idx] = wt;
                            }
                        }
                    }
                }
            }
        }
    }

    // ---------------- Barrier 1 + aggregation (last-arriving block) -------
    __threadfence();
    __syncthreads();
    if (tid == 0) s_flag = (atomicAdd(&g_done1, 1) == nb - 1) ? 1 : 0;
    __syncthreads();

    if (s_flag) {
        // dedupe hits; per-row adjustment sum(exp(v)-1); fixup list
        for (int i = tid; i < B; i += NTHREADS) sadj[i] = 0.0f;
        if (tid == 0) g_nfix = 0;
        __syncthreads();
        int n = g_nhits; if (n > CAP) n = CAP;
        for (int i = tid; i < n; i += NTHREADS) {
            int b = g_hit_b[i], t = g_hit_t[i];
            float v = g_hit_w[i];
            bool owner = true;
            for (int j = 0; j < n; j++) {
                if (j == i) continue;
                if (g_hit_b[j] == b && g_hit_t[j] == t) {
                    if (j < i) { owner = false; break; }
                    v += g_hit_w[j];
                }
            }
            if (owner) atomicAdd(&sadj[b], __expf(v) - 1.0f);
        }
        __syncthreads();
        if (tid < B) g_inv[tid] = 1.0f / ((float)nn + sadj[tid]);
        __syncthreads();
        for (int i = tid; i < n; i += NTHREADS) {
            int b = g_hit_b[i], t = g_hit_t[i];
            float v = g_hit_w[i];
            bool owner = true;
            for (int j = 0; j < n; j++) {
                if (j == i) continue;
                if (g_hit_b[j] == b && g_hit_t[j] == t) {
                    if (j < i) { owner = false; break; }
                    v += g_hit_w[j];
                }
            }
            if (owner) {
                int k = atomicAdd(&g_nfix, 1);
                if (k < CAP) {
                    g_fix_pos[k] = (long long)b * nn + t;
                    g_fix_val[k] = __expf(v) / ((float)nn + sadj[b]);
                }
            }
        }
        __syncthreads();
        __threadfence();
        if (tid == 0) { g_done1 = 0; g_phase = 1; }
    } else {
        if (tid == 0) { while (g_phase == 0) __nanosleep(64); }
        __syncthreads();
    }

    // ---------------- Phase D: constant fill + in-range fixups ------------
    if (tid < B) sinv[tid] = g_inv[tid];
    __syncthreads();

    const long long lim = (long long)B * nn;
    int n4 = out_size >> 2;
    int perF = (n4 + nb - 1) / nb;
    int s4 = bid * perF;
    int e4 = s4 + perF; if (e4 > n4) e4 = n4;

    if ((nn & 3) == 0) {
        int nn4 = nn >> 2;
        for (int i4 = s4 + tid; i4 < e4; i4 += NTHREADS) {
            long long pos = (long long)i4 << 2;
            float v = (pos < lim) ? sinv[i4 / nn4] : 0.0f;
            reinterpret_cast<float4*>(out)[i4] = make_float4(v, v, v, v);
        }
    } else {
        for (int i4 = s4 + tid; i4 < e4; i4 += NTHREADS) {
            #pragma unroll
            for (int c = 0; c < 4; c++) {
                long long pos = ((long long)i4 << 2) + c;
                out[pos] = (pos < lim) ? sinv[(int)(pos / nn)] : 0.0f;
            }
        }
    }
    // scalar tail (out_size % 4) — last block
    if (bid == nb - 1) {
        for (int p = (n4 << 2) + tid; p < out_size; p += NTHREADS)
            out[p] = ((long long)p < lim) ? sinv[(int)((long long)p / nn)] : 0.0f;
    }
    __syncthreads();

    // fixups owned by this block's chunk
    {
        int nf = g_nfix; if (nf > CAP) nf = CAP;
        for (int i = tid; i < nf; i += NTHREADS) {
            long long pos = g_fix_pos[i];
            long long i4  = pos >> 2;
            bool mine = (i4 >= s4 && i4 < e4) || (i4 >= n4 && bid == nb - 1);
            if (mine) out[pos] = g_fix_val[i];
        }
    }

    // ---------------- Phase E: reset for next replay ----------------------
    __threadfence();
    __syncthreads();
    if (tid == 0) {
        if (atomicAdd(&g_done2, 1) == nb - 1) {
            g_done2 = 0;
            g_nhits = 0;
            g_phase = 0;
        }
    }
}

extern "C" void kernel_launch(void* const* d_in, const int* in_sizes, int n_in,
                              void* d_out, int out_size) {
    // ---- Identify inputs by SIZE SIGNATURE (ordering-invariant) ----
    int iEI = 0, maxSz = 0;
    for (int i = 0; i < n_in; i++)
        if (in_sizes[i] > maxSz) { maxSz = in_sizes[i]; iEI = i; }
    int E = maxSz / 2;

    int iB = -1, iT = -1, iW = -1;
    for (int i = 0; i < n_in; i++) {
        if (i == iEI) continue;
        int s = in_sizes[i];
        if (s == E)                               { if (iT < 0) iT = i; else iW = i; }
        else if (s > 1 && (s % 96) == 0 && iB < 0) iB = i;
    }

    const int*   edge_index = (const int*)d_in[iEI];
    const int*   edge_type  = (const int*)d_in[iT];
    const int*   batch      = (const int*)d_in[iB];
    const float* edge_w     = (const float*)d_in[iW];

    int B  = in_sizes[iB] / 96;       // 64
    if (B > MAX_B) B = MAX_B;
    int nn = out_size / B;            // 50000 (int div absorbs trailing ALPHA slot)
    const int* heads = edge_index;
    const int* tails = edge_index + E;

    fused_kernel<<<NBLOCKS, NTHREADS>>>(heads, edge_type, tails, edge_w,
                                        batch, (float*)d_out,
                                        E, B, nn, out_size);
}